// round 5
// baseline (speedup 1.0000x reference)
#include <cuda_runtime.h>
#include <cuda_bf16.h>

// Problem constants (fixed by the dataset)
#define T 12
#define C 32
#define NMAX 100000
#define RSTRIDE 16          // padded row stride (floats) -> 64B rows

// LUT over scalar aggregate value a
#define LUT_ROWS 8192
#define A_RANGE  12.0f

// Scratch (no cudaMalloc allowed)
__device__ __align__(16) float g_deg[NMAX];              // sum of incoming w (no self loop)
__device__ float g_dinv[NMAX];
__device__ __align__(16) float g_xs[NMAX * RSTRIDE];     // dinv[n] * x[n,t], 64B rows
__device__ __align__(16) float g_aggraw[NMAX * RSTRIDE]; // sum_e w * xs[src]
__device__ __align__(16) float g_lut[(LUT_ROWS + 1) * C];

// Fused small params for node stage
__device__ float g_hw[C];   // head_w
__device__ float g_wp[T];   // softmax(att)
__device__ float g_hb;      // head_b

__device__ __forceinline__ float ex2f(float x) {
    float y;
    asm("ex2.approx.f32 %0, %1;" : "=f"(y) : "f"(x));
    return y;
}
__device__ __forceinline__ float tanh_acc(float v) {
    v = fminf(fmaxf(v, -20.0f), 20.0f);
    float e = ex2f(-2.885390082f * v);   // exp(-2v)
    return (1.0f - e) / (1.0f + e);
}
__device__ __forceinline__ float sigmoid_acc(float v) {
    v = fminf(fmaxf(v, -30.0f), 30.0f);
    float e = ex2f(-1.442695041f * v);   // exp(-v)
    return 1.0f / (1.0f + e);
}

// ---------------------------------------------------------------------------
// Stage 0: fused precompute + LUT build + scratch zero-fill.
// Every block redundantly computes the per-channel fused coefficients in smem
// (32x32 FMAs, negligible), then grid-stride fills its LUT slice and the
// aggraw/deg zero-fill (grid-stride float4 stores).
// ---------------------------------------------------------------------------
__global__ void lut_kernel(
    const float* __restrict__ wz, const float* __restrict__ bz,
    const float* __restrict__ wh, const float* __restrict__ bh,
    const float* __restrict__ lwz, const float* __restrict__ lbz,
    const float* __restrict__ lwh, const float* __restrict__ lbh,
    const float* __restrict__ att,
    const float* __restrict__ head_w, const float* __restrict__ head_b,
    int n)
{
    __shared__ float s_az[C], s_bz[C], s_ah[C], s_bh[C];
    int tid = threadIdx.x;
    if (tid < C) {
        float az = 0.f, bzs = 0.f, ah = 0.f, bhs = 0.f;
        #pragma unroll
        for (int k = 0; k < C; k++) {
            float lz = lwz[tid * 2 * C + k];
            float lh = lwh[tid * 2 * C + k];
            az  = fmaf(lz, wz[k], az);
            bzs = fmaf(lz, bz[k], bzs);
            ah  = fmaf(lh, wh[k], ah);
            bhs = fmaf(lh, bh[k], bhs);
        }
        s_az[tid] = az;
        s_bz[tid] = bzs + lbz[tid];
        s_ah[tid] = ah;
        s_bh[tid] = bhs + lbh[tid];
        if (blockIdx.x == 0) g_hw[tid] = head_w[tid];
    }
    if (blockIdx.x == 0 && tid == 0) {
        float m = -1e30f;
        for (int t = 0; t < T; t++) m = fmaxf(m, att[t]);
        float ex[T]; float s = 0.f;
        for (int t = 0; t < T; t++) { ex[t] = ex2f(1.442695041f * (att[t] - m)); s += ex[t]; }
        float inv = 1.0f / s;
        for (int t = 0; t < T; t++) g_wp[t] = ex[t] * inv;
        g_hb = head_b[0];
    }
    __syncthreads();

    int gtid = blockIdx.x * blockDim.x + tid;
    int gstr = gridDim.x * blockDim.x;

    // Zero-fill aggraw (padded) and deg with float4 stores
    {
        float4 z = make_float4(0.f, 0.f, 0.f, 0.f);
        int qa = (n * RSTRIDE) >> 2;
        for (int i = gtid; i < qa; i += gstr) ((float4*)g_aggraw)[i] = z;
        int qd = n >> 2;
        for (int i = gtid; i < qd; i += gstr) ((float4*)g_deg)[i] = z;
    }

    int total = (LUT_ROWS + 1) * C;
    for (int i = gtid; i < total; i += gstr) {
        int r = i >> 5;
        int c = i & 31;
        float a = -A_RANGE + (2.0f * A_RANGE / LUT_ROWS) * (float)r;
        float z = sigmoid_acc(fmaf(a, s_az[c], s_bz[c]));
        float h = tanh_acc(fmaf(a, s_ah[c], s_bh[c]));
        g_lut[i] = (1.0f - z) * h;
    }
}

// ---------------------------------------------------------------------------
// Stage 1: degree scatter-add, 4 edges/thread with wide loads
// ---------------------------------------------------------------------------
__global__ void deg_kernel(const int* __restrict__ ei,
                           const float* __restrict__ ew, int e) {
    int i0 = 4 * (blockIdx.x * blockDim.x + threadIdx.x);
    if (i0 + 3 < e) {
        int4   d = *(const int4*)(ei + e + i0);   // destinations
        float4 w = *(const float4*)(ew + i0);
        atomicAdd(&g_deg[d.x], w.x);
        atomicAdd(&g_deg[d.y], w.y);
        atomicAdd(&g_deg[d.z], w.z);
        atomicAdd(&g_deg[d.w], w.w);
    } else {
        for (int i = i0; i < e; i++)
            atomicAdd(&g_deg[__ldg(ei + e + i)], __ldg(ew + i));
    }
}

// ---------------------------------------------------------------------------
// Stage 2: dinv = rsqrt(1 + deg) (self-loop folded); xs = dinv * x (padded rows)
// ---------------------------------------------------------------------------
__global__ void xs_kernel(const float* __restrict__ x, int n) {
    int i = blockIdx.x * blockDim.x + threadIdx.x;
    if (i >= n) return;
    float dv = rsqrtf(1.0f + g_deg[i]);
    g_dinv[i] = dv;
    const float4* xr = (const float4*)(x + (size_t)i * T);
    float4* o = (float4*)(g_xs + (size_t)i * RSTRIDE);
    #pragma unroll
    for (int k = 0; k < 3; k++) {
        float4 v = xr[k];
        v.x *= dv; v.y *= dv; v.z *= dv; v.w *= dv;
        o[k] = v;
    }
}

// ---------------------------------------------------------------------------
// Stage 3: edge aggregation: agg_raw[d,:] += w * xs[s,:]
// 4 edges/thread, wide edge loads, 64B-aligned gathers, 3 v4 REDGs per edge.
// ---------------------------------------------------------------------------
__device__ __forceinline__ void edge_one(int s, int d, float w) {
    const float4* xr = (const float4*)(g_xs + (size_t)s * RSTRIDE);
    float* dst = g_aggraw + (size_t)d * RSTRIDE;
    #pragma unroll
    for (int k = 0; k < 3; k++) {
        float4 v = __ldg(xr + k);
        float a = v.x * w, b = v.y * w, c = v.z * w, q = v.w * w;
        asm volatile("red.global.add.v4.f32 [%0], {%1,%2,%3,%4};"
                     :: "l"(dst + 4 * k), "f"(a), "f"(b), "f"(c), "f"(q)
                     : "memory");
    }
}

__global__ void edge_agg_kernel(const int* __restrict__ ei,
                                const float* __restrict__ ew, int e) {
    int i0 = 4 * (blockIdx.x * blockDim.x + threadIdx.x);
    if (i0 + 3 < e) {
        int4   s = *(const int4*)(ei + i0);
        int4   d = *(const int4*)(ei + e + i0);
        float4 w = *(const float4*)(ew + i0);
        edge_one(s.x, d.x, w.x);
        edge_one(s.y, d.y, w.y);
        edge_one(s.z, d.z, w.z);
        edge_one(s.w, d.w, w.w);
    } else {
        for (int i = i0; i < e; i++)
            edge_one(__ldg(ei + i), __ldg(ei + e + i), __ldg(ew + i));
    }
}

// ---------------------------------------------------------------------------
// Stage 4: warp-per-node. lane = channel.
//   a_t = dinv * (agg_raw + xs); acc_c = sum_t wp_t * lerp(LUT, a_t)[c]
//   out = hb + sum_c hw_c * relu(acc_c)
// ---------------------------------------------------------------------------
__global__ void node_kernel(float* __restrict__ out, int n) {
    int gtid = blockIdx.x * blockDim.x + threadIdx.x;
    int i = gtid >> 5;        // node
    int lane = gtid & 31;     // channel
    if (i >= n) return;

    float hw = g_hw[lane];
    float wp[T];
    #pragma unroll
    for (int t = 0; t < T; t++) wp[t] = g_wp[t];

    float dv = g_dinv[i];
    const float4* ag = (const float4*)(g_aggraw + (size_t)i * RSTRIDE);
    const float4* xp = (const float4*)(g_xs + (size_t)i * RSTRIDE);
    float a[T];
    #pragma unroll
    for (int k = 0; k < 3; k++) {
        float4 u = ag[k];
        float4 v = xp[k];
        a[4 * k + 0] = dv * (u.x + v.x);
        a[4 * k + 1] = dv * (u.y + v.y);
        a[4 * k + 2] = dv * (u.z + v.z);
        a[4 * k + 3] = dv * (u.w + v.w);
    }

    const float invD = (float)LUT_ROWS / (2.0f * A_RANGE);
    const float pmax = (float)LUT_ROWS - 0.001f;

    float acc = 0.0f;
    #pragma unroll
    for (int t = 0; t < T; t++) {
        float pos = fmaf(a[t], invD, A_RANGE * invD);
        pos = fminf(fmaxf(pos, 0.0f), pmax);
        int idx = (int)pos;
        float f = pos - (float)idx;
        const float* row = g_lut + idx * C + lane;
        float r0 = __ldg(row);
        float r1 = __ldg(row + C);
        float w1 = wp[t] * f;
        float w0 = wp[t] - w1;
        acc = fmaf(r0, w0, fmaf(r1, w1, acc));
    }

    float v = fmaxf(acc, 0.0f) * hw;
    #pragma unroll
    for (int off = 16; off > 0; off >>= 1)
        v += __shfl_xor_sync(0xFFFFFFFFu, v, off);
    if (lane == 0) out[i] = v + g_hb;
}

// ---------------------------------------------------------------------------
extern "C" void kernel_launch(void* const* d_in, const int* in_sizes, int n_in,
                              void* d_out, int out_size) {
    const float* x      = (const float*)d_in[0];
    const int*   ei     = (const int*)  d_in[1];
    const float* ew     = (const float*)d_in[2];
    const float* wz     = (const float*)d_in[3];
    const float* bz     = (const float*)d_in[4];
    // d_in[5], d_in[6]: w_r, b_r (unused: reset gate multiplies H=0)
    const float* wh     = (const float*)d_in[7];
    const float* bh     = (const float*)d_in[8];
    const float* lwz    = (const float*)d_in[9];
    const float* lbz    = (const float*)d_in[10];
    // d_in[11], d_in[12]: lw_r, lb_r (unused)
    const float* lwh    = (const float*)d_in[13];
    const float* lbh    = (const float*)d_in[14];
    const float* att    = (const float*)d_in[15];
    const float* head_w = (const float*)d_in[16];
    const float* head_b = (const float*)d_in[17];
    float* out = (float*)d_out;

    int n = in_sizes[0] / T;   // 100000
    int e = in_sizes[2];       // 3.2M

    const int B = 256;
    lut_kernel<<<((LUT_ROWS + 1) * C + B - 1) / B, B>>>(
        wz, bz, wh, bh, lwz, lbz, lwh, lbh, att, head_w, head_b, n);
    deg_kernel<<<((e + 3) / 4 + B - 1) / B, B>>>(ei, ew, e);
    xs_kernel<<<(n + B - 1) / B, B>>>(x, n);
    edge_agg_kernel<<<((e + 3) / 4 + B - 1) / B, B>>>(ei, ew, e);
    node_kernel<<<(n * 32 + B - 1) / B, B>>>(out, n);
}